// round 12
// baseline (speedup 1.0000x reference)
#include <cuda_runtime.h>
#include <cstdint>

#define HID 128
#define T_STEPS 2048
#define BATCH 64
#define NOUT 5
#define MROWS (BATCH * T_STEPS)   // 131072

// -------------------- scratch (device globals; no allocation) --------------------
__device__ float g_xw[(size_t)MROWS * 384];   // input-projection buffer
__device__ float g_h0[(size_t)MROWS * HID];   // layer output ping
__device__ float g_h1[(size_t)MROWS * HID];   // layer output pong

// -------------------- packed f32x2 helpers --------------------
__device__ __forceinline__ unsigned long long pack2(float lo, float hi) {
    unsigned long long r;
    asm("mov.b64 %0, {%1, %2};" : "=l"(r) : "f"(lo), "f"(hi));
    return r;
}
__device__ __forceinline__ void unpack2(unsigned long long v, float& lo, float& hi) {
    asm("mov.b64 {%0, %1}, %2;" : "=f"(lo), "=f"(hi) : "l"(v));
}
#define FMA2(d, a, b, c) \
    asm("fma.rn.f32x2 %0, %1, %2, %3;" : "=l"(d) : "l"(a), "l"(b), "l"(c))

// ============================================================================
// GEMM: C[M,384-tile] = A[M,128] @ W[128,384] + bias_in (+ brec for cols<256)
// grid = (M/128, 3), 256 threads, dynamic smem = As(128x132) + Bs(128x128)
// ============================================================================
__global__ __launch_bounds__(256, 1)
void gemm128(const float* __restrict__ A, const float* __restrict__ W,
             const float* __restrict__ bias, const float* __restrict__ brec,
             float* __restrict__ C, int M) {
    extern __shared__ float smem[];
    float* As = smem;              // As[k][m], pitch 132
    float* Bs = smem + 128 * 132;  // Bs[k][n], pitch 128

    const int m0 = blockIdx.x * 128;
    const int n0 = blockIdx.y * 128;
    const int tid = threadIdx.x;

    for (int idx = tid; idx < 128 * 32; idx += 256) {
        int r = idx >> 5, c4 = idx & 31;
        float4 v = *(const float4*)(A + (size_t)(m0 + r) * 128 + c4 * 4);
        As[(c4 * 4 + 0) * 132 + r] = v.x;
        As[(c4 * 4 + 1) * 132 + r] = v.y;
        As[(c4 * 4 + 2) * 132 + r] = v.z;
        As[(c4 * 4 + 3) * 132 + r] = v.w;
    }
    for (int idx = tid; idx < 128 * 32; idx += 256) {
        int k = idx >> 5, c4 = idx & 31;
        *(float4*)&Bs[k * 128 + c4 * 4] =
            *(const float4*)(W + (size_t)k * 384 + n0 + c4 * 4);
    }
    __syncthreads();

    const int tx = tid & 15, ty = tid >> 4;
    const int mr = ty * 8, nc = tx * 8;

    unsigned long long acc[8][4];
#pragma unroll
    for (int i = 0; i < 8; i++)
#pragma unroll
        for (int jj = 0; jj < 4; jj++) acc[i][jj] = 0ULL;

#pragma unroll 8
    for (int k = 0; k < 128; k++) {
        float4 a0 = *(const float4*)&As[k * 132 + mr];
        float4 a1 = *(const float4*)&As[k * 132 + mr + 4];
        ulonglong2 b0 = *(const ulonglong2*)&Bs[k * 128 + nc];
        ulonglong2 b1 = *(const ulonglong2*)&Bs[k * 128 + nc + 4];
        float av[8] = {a0.x, a0.y, a0.z, a0.w, a1.x, a1.y, a1.z, a1.w};
        unsigned long long bp[4] = {b0.x, b0.y, b1.x, b1.y};
#pragma unroll
        for (int i = 0; i < 8; i++) {
            unsigned long long ap = pack2(av[i], av[i]);
#pragma unroll
            for (int jj = 0; jj < 4; jj++) FMA2(acc[i][jj], ap, bp[jj], acc[i][jj]);
        }
    }

    float bv[8];
#pragma unroll
    for (int c = 0; c < 8; c++) {
        int n = n0 + nc + c;
        bv[c] = bias[n] + (n < 256 ? brec[n] : 0.0f);
    }

#pragma unroll
    for (int i = 0; i < 8; i++) {
        float o[8];
#pragma unroll
        for (int jj = 0; jj < 4; jj++) unpack2(acc[i][jj], o[2 * jj], o[2 * jj + 1]);
#pragma unroll
        for (int c = 0; c < 8; c++) o[c] += bv[c];
        float* cp = C + (size_t)(m0 + mr + i) * 384 + n0 + nc;
        *(float4*)cp = make_float4(o[0], o[1], o[2], o[3]);
        *(float4*)(cp + 4) = make_float4(o[4], o[5], o[6], o[7]);
    }
}

// ============================================================================
// GRU scan v6: one CTA/batch, 256 threads (reg budget 256/thread).
//  Thread t owns:
//    - FULL gate column t   (t<128: z_t ; t>=128: r_{t-128})  -> 64 f32x2 regs
//    - HALF hh column 256+(t&127), rows [64*(t>>7), +64)      -> 32 f32x2 regs
//  Tail on threads t<128 (1 warp/SMSP): hh combined by one add; xh x-part is
//  prefetched into the same thread's registers (no smem hop).
// ============================================================================
__global__ __launch_bounds__(256, 1)
void scan_kernel(const float* __restrict__ xw, const float* __restrict__ rk,
                 const float* __restrict__ brec, float* __restrict__ hout) {
    const int b = blockIdx.x;
    const int t = threadIdx.x;        // 0..255
    const int m = t & 127;            // h index for half-col / tail
    const int hi = t >> 7;            // which half of hh column

    __shared__ __align__(16) float h_sh[HID];
    __shared__ float g_sh[256];
    __shared__ float hpart[256];

    // full column t (z/r ranges)
    unsigned long long wf[64];
#pragma unroll
    for (int i = 0; i < 64; i++) {
        float a0 = rk[(size_t)(2 * i) * 384 + t];
        float a1 = rk[(size_t)(2 * i + 1) * 384 + t];
        wf[i] = pack2(a0, a1);
    }
    // half of hh column 256+m, rows 64*hi .. 64*hi+63
    unsigned long long wh[32];
    {
        const float* rkc = rk + (size_t)(64 * hi) * 384 + 256 + m;
#pragma unroll
        for (int i = 0; i < 32; i++) {
            float a0 = rkc[(size_t)(2 * i) * 384];
            float a1 = rkc[(size_t)(2 * i + 1) * 384];
            wh[i] = pack2(a0, a1);
        }
    }

    const float brh = brec[256 + m];
    float h_reg = 0.0f;
    if (t < HID) h_sh[t] = 0.0f;

    const float* xrow  = xw + (size_t)b * T_STEPS * 384 + t;        // full col
    const float* xrowh = xw + (size_t)b * T_STEPS * 384 + 256 + m;  // hh col
    float xv0 = xrow[0],   xv1 = xrow[384];
    float xh0 = xrowh[0],  xh1 = xrowh[384];
    float* hrow = hout + (size_t)b * T_STEPS * HID + m;  // tail: t<128
    __syncthreads();

    for (int tstep = 0; tstep < T_STEPS; tstep++) {
        int tp = (tstep + 2 < T_STEPS) ? tstep + 2 : T_STEPS - 1;
        float xv2 = xrow[(size_t)tp * 384];
        float xh2 = xrowh[(size_t)tp * 384];

        // full-col dot (128 MACs) + half-col dot (64 MACs), pipelined LDS
        const ulonglong2* hp = (const ulonglong2*)h_sh;
        const ulonglong2* hq = hp + 16 * hi;
        unsigned long long a0 = 0ULL, a1 = 0ULL;   // full col, 2 chains
        unsigned long long c0 = 0ULL, c1 = 0ULL;   // half col, 2 chains
        ulonglong2 u0 = hp[0], u1 = hp[1];
        ulonglong2 v0 = hq[0];
#pragma unroll
        for (int i = 0; i < 16; i++) {
            ulonglong2 nu0, nu1, nv0;
            if (i < 15) { nu0 = hp[2 * i + 2]; nu1 = hp[2 * i + 3]; nv0 = hq[i + 1]; }
            FMA2(a0, u0.x, wf[4 * i + 0], a0);
            FMA2(a1, u0.y, wf[4 * i + 1], a1);
            FMA2(c0, v0.x, wh[2 * i + 0], c0);
            FMA2(a0, u1.x, wf[4 * i + 2], a0);
            FMA2(a1, u1.y, wf[4 * i + 3], a1);
            FMA2(c1, v0.y, wh[2 * i + 1], c1);
            u0 = nu0; u1 = nu1; v0 = nv0;
        }
        float l0, f0, l1, f1;
        unpack2(a0, l0, f0);
        unpack2(a1, l1, f1);
        g_sh[t] = (l0 + l1) + (f0 + f1) + xv0;   // z/r: biases pre-folded in xw
        unpack2(c0, l0, f0);
        unpack2(c1, l1, f1);
        hpart[t] = (l0 + l1) + (f0 + f1);
        __syncthreads();

        if (t < HID) {
            float gz = g_sh[t];
            float gr = g_sh[128 + t];
            float ph = hpart[t] + hpart[128 + t] + brh;
            float z = __fdividef(1.0f, 1.0f + __expf(-gz));
            float r = __fdividef(1.0f, 1.0f + __expf(-gr));
            float e2 = __expf(-2.0f * (xh0 + r * ph));
            float hh = __fdividef(2.0f, 1.0f + e2) - 1.0f;   // tanh
            float hn = z * h_reg + (1.0f - z) * hh;
            h_reg = hn;
            h_sh[t] = hn;
            hrow[(size_t)tstep * HID] = hn;
        }
        __syncthreads();

        xv0 = xv1; xv1 = xv2;
        xh0 = xh1; xh1 = xh2;
    }
}

// ============================================================================
// Output head: out[M,5] = H[M,128] @ wo[128,5] + bo
// ============================================================================
__global__ __launch_bounds__(256, 1)
void outproj(const float* __restrict__ H, const float* __restrict__ wo,
             const float* __restrict__ bo, float* __restrict__ out, int M) {
    __shared__ float ws[HID * NOUT];
    __shared__ float bs[NOUT];
    for (int i = threadIdx.x; i < HID * NOUT; i += blockDim.x) ws[i] = wo[i];
    if (threadIdx.x < NOUT) bs[threadIdx.x] = bo[threadIdx.x];
    __syncthreads();

    int r = blockIdx.x * blockDim.x + threadIdx.x;
    if (r >= M) return;

    const float4* hr = (const float4*)(H + (size_t)r * HID);
    float acc[NOUT];
#pragma unroll
    for (int o = 0; o < NOUT; o++) acc[o] = bs[o];

#pragma unroll
    for (int k4 = 0; k4 < 32; k4++) {
        float4 v = hr[k4];
#pragma unroll
        for (int o = 0; o < NOUT; o++) {
            acc[o] += v.x * ws[(k4 * 4 + 0) * NOUT + o];
            acc[o] += v.y * ws[(k4 * 4 + 1) * NOUT + o];
            acc[o] += v.z * ws[(k4 * 4 + 2) * NOUT + o];
            acc[o] += v.w * ws[(k4 * 4 + 3) * NOUT + o];
        }
    }
#pragma unroll
    for (int o = 0; o < NOUT; o++) out[(size_t)r * NOUT + o] = acc[o];
}

// ============================================================================
// Launcher: single stream, sequential (allocation-free).
// ============================================================================
extern "C" void kernel_launch(void* const* d_in, const int* in_sizes, int n_in,
                              void* d_out, int out_size) {
    const float* x   = (const float*)d_in[0];
    const float* k0  = (const float*)d_in[1];
    const float* rk0 = (const float*)d_in[2];
    const float* b0  = (const float*)d_in[3];
    const float* k1  = (const float*)d_in[4];
    const float* rk1 = (const float*)d_in[5];
    const float* b1  = (const float*)d_in[6];
    const float* k2  = (const float*)d_in[7];
    const float* rk2 = (const float*)d_in[8];
    const float* b2  = (const float*)d_in[9];
    const float* wo  = (const float*)d_in[10];
    const float* bo  = (const float*)d_in[11];
    float* out = (float*)d_out;

    float *xwp, *h0p, *h1p;
    cudaGetSymbolAddress((void**)&xwp, g_xw);
    cudaGetSymbolAddress((void**)&h0p, g_h0);
    cudaGetSymbolAddress((void**)&h1p, g_h1);

    const int M = MROWS;
    const size_t smem = (128 * 132 + 128 * 128) * sizeof(float);  // 133 KB
    cudaFuncSetAttribute(gemm128, cudaFuncAttributeMaxDynamicSharedMemorySize,
                         (int)smem);

    dim3 ggrid(M / 128, 3);

    // Layer 0
    gemm128<<<ggrid, 256, smem>>>(x, k0, b0, b0 + 384, xwp, M);
    scan_kernel<<<BATCH, 256>>>(xwp, rk0, b0 + 384, h0p);
    // Layer 1
    gemm128<<<ggrid, 256, smem>>>(h0p, k1, b1, b1 + 384, xwp, M);
    scan_kernel<<<BATCH, 256>>>(xwp, rk1, b1 + 384, h1p);
    // Layer 2
    gemm128<<<ggrid, 256, smem>>>(h1p, k2, b2, b2 + 384, xwp, M);
    scan_kernel<<<BATCH, 256>>>(xwp, rk2, b2 + 384, h0p);
    // Output head
    outproj<<<(MROWS + 255) / 256, 256>>>(h0p, wo, bo, out, MROWS);
}